// round 10
// baseline (speedup 1.0000x reference)
#include <cuda_runtime.h>
#include <cstdint>

#define BB  2048
#define IN  512
#define NF  256
#define NP  256
#define EPS 1e-8f

// ---------------------------------------------------------------------------
// Device globals (allocation-free rule)
// ---------------------------------------------------------------------------
__device__ unsigned g_xq[(NF / 4) * BB];   // [f4][b] packed u8x4 of 255*sigmoid(x@W^T)
__device__ unsigned g_pq[(NF / 4) * NP];   // [f4][p] packed u8x4 of 255*sigmoid(prototypes)
__device__ float g_SxP[4 * BB];            // exact fp32 partial row sums of x_sig
__device__ float g_Sp[NP];                 // exact fp32 row sums of p_sig

__device__ __forceinline__ float sigmoidf(float v) {
    return 1.0f / (1.0f + __expf(-v));
}

__device__ __forceinline__ unsigned q8(float s) {      // s in (0,1) -> round(255 s)
    return __float2uint_rn(s * 255.0f);
}

__device__ __forceinline__ unsigned pack4(float a, float b, float c, float d) {
    return q8(a) | (q8(b) << 8) | (q8(c) << 16) | (q8(d) << 24);
}

__device__ __forceinline__ uint32_t smem_u32(const void* p) {
    uint32_t a;
    asm("{ .reg .u64 t; cvta.to.shared.u64 t, %1; cvt.u32.u64 %0, t; }"
        : "=r"(a) : "l"(p));
    return a;
}

__device__ __forceinline__ uint32_t tf32r(float v) {
    uint32_t u;
    asm("cvt.rna.tf32.f32 %0, %1;" : "=r"(u) : "f"(v));
    return u;
}

__device__ __forceinline__ void ldsm_x4(uint32_t& r0, uint32_t& r1,
                                        uint32_t& r2, uint32_t& r3, uint32_t addr) {
    asm volatile("ldmatrix.sync.aligned.m8n8.x4.shared.b16 {%0,%1,%2,%3}, [%4];"
                 : "=r"(r0), "=r"(r1), "=r"(r2), "=r"(r3) : "r"(addr));
}

__device__ __forceinline__ void mma_tf32(float* d, const uint32_t* a, const uint32_t* b) {
    asm volatile(
        "mma.sync.aligned.m16n8k8.row.col.f32.tf32.tf32.f32 "
        "{%0,%1,%2,%3}, {%4,%5,%6,%7}, {%8,%9}, {%0,%1,%2,%3};"
        : "+f"(d[0]), "+f"(d[1]), "+f"(d[2]), "+f"(d[3])
        : "r"(a[0]), "r"(a[1]), "r"(a[2]), "r"(a[3]), "r"(b[0]), "r"(b[1]));
}

// ---------------------------------------------------------------------------
// Fused Kernel: GEMM CTAs (blockIdx.x < 32) + prototype CTAs (blockIdx.x == 32)
// GEMM mainloop identical to R8 (banked). Epilogues write packed u8x4.
// ---------------------------------------------------------------------------
#define KC      32
#define ASTR    36                      // smem row stride in floats (144B)
#define TILE_FL (64 * ASTR)             // floats per buffer

__global__ void __launch_bounds__(256, 1)
feat_gemm_kernel(const float* __restrict__ x,
                 const float* __restrict__ features,
                 const float* __restrict__ prototypes) {
    __shared__ __align__(16) float As[2][TILE_FL];
    __shared__ __align__(16) float Bs[2][TILE_FL];

    const int tid  = threadIdx.x;

    // ======================= prototype path =======================
    if (blockIdx.x == 32) {
        float (*t)[68] = (float(*)[68])&As[0][0];     // 64 x 68 tile (17.4 KB <= As)
        const int p0 = blockIdx.y * 64;
        float spacc = 0.f;

        for (int fc = 0; fc < 4; fc++) {
            #pragma unroll
            for (int i = 0; i < 16; i++) {
                int idx = tid + i * 256;              // 0..4095
                int p = idx >> 6, f = idx & 63;
                t[p][f] = sigmoidf(prototypes[(size_t)(p0 + p) * NF + fc * 64 + f]);
            }
            __syncthreads();
            // pack 64p x 16 f4-groups -> g_pq
            #pragma unroll
            for (int i = 0; i < 4; i++) {
                int idx = tid + i * 256;              // 0..1023
                int g = idx >> 6, p = idx & 63;
                float4 v = *(const float4*)&t[p][g * 4];
                g_pq[(size_t)(fc * 16 + g) * NP + p0 + p] = pack4(v.x, v.y, v.z, v.w);
            }
            if (tid < 64) {
                float s = 0.f;
                #pragma unroll 16
                for (int f = 0; f < 64; f++) s += t[tid][f];
                spacc += s;
            }
            __syncthreads();
        }
        if (tid < 64) g_Sp[p0 + tid] = spacc;
        return;
    }

    // ========================= GEMM path =========================
    const int wid  = tid >> 5;
    const int lane = tid & 31;
    const int b0 = blockIdx.x * 64;
    const int f0 = blockIdx.y * 64;
    const int m_off = (wid & 1) * 32;        // m in {0, 32}
    const int n_off = (wid >> 1) * 16;       // n in {0, 16, 32, 48}

    int lrow[2], lkq[2];
    #pragma unroll
    for (int i = 0; i < 2; i++) {
        int idx = tid + i * 256;
        lrow[i] = idx >> 3;                  // 0..63
        lkq[i]  = idx & 7;                   // float4 slot along k
    }

    const uint32_t sA = smem_u32(As);
    const uint32_t sB = smem_u32(Bs);
    const uint32_t a_off = (uint32_t)(((lane & 15) + m_off) * ASTR + ((lane >> 4) & 1) * 4) * 4;
    const uint32_t b_off = (uint32_t)((((lane & 7) + ((lane >> 4) & 1) * 8) + n_off) * ASTR
                                      + ((lane >> 3) & 1) * 4) * 4;

    // prefetch reg sets for chunks 0 and 1 (distance-2 pipeline)
    float4 av[2][2], bv[2][2];
    #pragma unroll
    for (int s = 0; s < 2; s++)
        #pragma unroll
        for (int i = 0; i < 2; i++) {
            av[s][i] = *(const float4*)&x[(size_t)(b0 + lrow[i]) * IN + s * KC + lkq[i] * 4];
            bv[s][i] = *(const float4*)&features[(size_t)(f0 + lrow[i]) * IN + s * KC + lkq[i] * 4];
        }

    float acc[2][2][4] = {};                 // [mt][nt][4]

    #pragma unroll 2
    for (int c = 0; c < IN / KC; c++) {
        const int buf = c & 1;

        #pragma unroll
        for (int i = 0; i < 2; i++) {
            uint4 ua = make_uint4(tf32r(av[buf][i].x), tf32r(av[buf][i].y),
                                  tf32r(av[buf][i].z), tf32r(av[buf][i].w));
            uint4 ub = make_uint4(tf32r(bv[buf][i].x), tf32r(bv[buf][i].y),
                                  tf32r(bv[buf][i].z), tf32r(bv[buf][i].w));
            *(uint4*)&As[buf][lrow[i] * ASTR + lkq[i] * 4] = ua;
            *(uint4*)&Bs[buf][lrow[i] * ASTR + lkq[i] * 4] = ub;
        }

        if (c + 2 < IN / KC) {
            const int k0 = (c + 2) * KC;
            #pragma unroll
            for (int i = 0; i < 2; i++) {
                av[buf][i] = *(const float4*)&x[(size_t)(b0 + lrow[i]) * IN + k0 + lkq[i] * 4];
                bv[buf][i] = *(const float4*)&features[(size_t)(f0 + lrow[i]) * IN + k0 + lkq[i] * 4];
            }
        }

        __syncthreads();

        const uint32_t baseA = sA + (uint32_t)buf * TILE_FL * 4;
        const uint32_t baseB = sB + (uint32_t)buf * TILE_FL * 4;

        #pragma unroll
        for (int s = 0; s < 4; s++) {
            const uint32_t kb = (uint32_t)(s * 8) * 4;
            uint32_t aa[2][4], bb[4];
            ldsm_x4(aa[0][0], aa[0][1], aa[0][2], aa[0][3], baseA + a_off + kb);
            ldsm_x4(aa[1][0], aa[1][1], aa[1][2], aa[1][3], baseA + a_off + kb + 16 * ASTR * 4);
            ldsm_x4(bb[0], bb[1], bb[2], bb[3], baseB + b_off + kb);
            #pragma unroll
            for (int mt = 0; mt < 2; mt++)
                #pragma unroll
                for (int nt = 0; nt < 2; nt++)
                    mma_tf32(acc[mt][nt], aa[mt], &bb[nt * 2]);
        }
    }

    // ---- epilogue: sigmoid -> Csm [f][b]; then quantize/pack + exact Sx ----
    float* Csm = &As[0][0];                  // 64 x 68 overlay
    #define CSTR 68
    __syncthreads();

    {
        const int mrow = m_off + (lane >> 2);
        const int ncol = n_off + 2 * (lane & 3);
        #pragma unroll
        for (int mt = 0; mt < 2; mt++) {
            #pragma unroll
            for (int nt = 0; nt < 2; nt++) {
                const int m = mrow + mt * 16;
                const int n = ncol + nt * 8;
                Csm[(n    ) * CSTR + m    ] = sigmoidf(acc[mt][nt][0]);
                Csm[(n + 1) * CSTR + m    ] = sigmoidf(acc[mt][nt][1]);
                Csm[(n    ) * CSTR + m + 8] = sigmoidf(acc[mt][nt][2]);
                Csm[(n + 1) * CSTR + m + 8] = sigmoidf(acc[mt][nt][3]);
            }
        }
    }
    __syncthreads();

    // pack 16 f4-groups x 64 b -> g_xq (coalesced u32 stores)
    #pragma unroll
    for (int i = 0; i < 4; i++) {
        int idx = tid + i * 256;             // 0..1023
        int g = idx >> 6, b = idx & 63;
        unsigned q = pack4(Csm[(4 * g + 0) * CSTR + b], Csm[(4 * g + 1) * CSTR + b],
                           Csm[(4 * g + 2) * CSTR + b], Csm[(4 * g + 3) * CSTR + b]);
        g_xq[(size_t)(f0 / 4 + g) * BB + b0 + b] = q;
    }

    // exact Sx partials: threads 0..63 sum their b-column over this CTA's 64 f's
    if (tid < 64) {
        float s = 0.f;
        #pragma unroll 16
        for (int f = 0; f < 64; f++) s += Csm[f * CSTR + tid];
        g_SxP[blockIdx.y * BB + b0 + tid] = s;
    }
}

// ---------------------------------------------------------------------------
// Kernel C: Tversky core, v4 — int8 SIMD.
// I[b,p] = sum_f min(xs,ps) ~= (1/255) * sum_f4 dp4a(vminu4(xq,pq), 1x4)
// Full 256-f tile resident in smem (packed): ONE barrier.
// 512 threads, warp grid 4(b) x 4(p), warp tile 16x16, lane tile 4b x 2p.
// grid (32, 4) = 128 CTAs.
// ---------------------------------------------------------------------------
__global__ void __launch_bounds__(512)
tversky_kernel(const float* __restrict__ bias,
               const float* __restrict__ alphap,
               const float* __restrict__ betap,
               float* __restrict__ out) {
    __shared__ unsigned xq[64][64];    // [f4][b]  16 KB (all 256 f)
    __shared__ unsigned pq[64][64];    // [f4][p]  16 KB

    const int tid = threadIdx.x;
    const int lane = tid & 31;
    const int wid  = tid >> 5;
    const int wi = wid & 3;            // warp p index
    const int wj = wid >> 2;           // warp b index
    const int li = lane & 7;           // lane p index (x2)
    const int lj = lane >> 3;          // lane b index (x4)
    const int b0 = blockIdx.x * 64;
    const int p0 = blockIdx.y * 64;

    const int bcol = wj * 16 + lj * 4;
    const int pcol = wi * 16 + li * 2;

    // fill smem: 1024 uint4 per array, 2 per thread
    #pragma unroll
    for (int i = 0; i < 2; i++) {
        int idx = tid + i * 512;           // 0..1023
        int r = idx >> 4;                  // f4 row 0..63
        int q = (idx & 15) * 4;            // u32 quad
        *(uint4*)&xq[r][q] = *(const uint4*)&g_xq[(size_t)r * BB + b0 + q];
        *(uint4*)&pq[r][q] = *(const uint4*)&g_pq[(size_t)r * NP + p0 + q];
    }
    __syncthreads();

    unsigned acc[4][2] = {};

    #pragma unroll 8
    for (int f4 = 0; f4 < 64; f4++) {
        uint4 a = *(const uint4*)&xq[f4][bcol];
        uint2 p = *(const uint2*)&pq[f4][pcol];
        unsigned av[4] = {a.x, a.y, a.z, a.w};
        #pragma unroll
        for (int i = 0; i < 4; i++) {
            acc[i][0] = __dp4a(__vminu4(av[i], p.x), 0x01010101u, acc[i][0]);
            acc[i][1] = __dp4a(__vminu4(av[i], p.y), 0x01010101u, acc[i][1]);
        }
    }

    const float alpha = *alphap;
    const float beta  = *betap;
    const float inv255 = 1.0f / 255.0f;

    float bi[2], spv[2];
    #pragma unroll
    for (int j = 0; j < 2; j++) {
        int p = p0 + pcol + j;
        bi[j]  = bias[p];
        spv[j] = g_Sp[p];
    }

    #pragma unroll
    for (int i = 0; i < 4; i++) {
        int b = b0 + bcol + i;
        float Sx = g_SxP[b] + g_SxP[BB + b] + g_SxP[2 * BB + b] + g_SxP[3 * BB + b];
        float2 o;
        #pragma unroll
        for (int j = 0; j < 2; j++) {
            float I = (float)acc[i][j] * inv255;
            float denom = I + alpha * (Sx - I) + beta * (spv[j] - I) + EPS;
            ((float*)&o)[j] = I / denom + bi[j];
        }
        *(float2*)&out[(size_t)b * NP + p0 + pcol] = o;
    }
}

// ---------------------------------------------------------------------------
// Launch. Inputs: x, features, prototypes, bias, alpha, beta.
// ---------------------------------------------------------------------------
extern "C" void kernel_launch(void* const* d_in, const int* in_sizes, int n_in,
                              void* d_out, int out_size) {
    const float* x          = (const float*)d_in[0];
    const float* features   = (const float*)d_in[1];
    const float* prototypes = (const float*)d_in[2];
    const float* bias       = (const float*)d_in[3];
    const float* alpha      = (const float*)d_in[4];
    const float* beta       = (const float*)d_in[5];
    float* out = (float*)d_out;

    feat_gemm_kernel<<<dim3(33, 4), 256>>>(x, features, prototypes);
    tversky_kernel<<<dim3(BB / 64, NP / 64), 512>>>(bias, alpha, beta, out);
}

// round 12
// speedup vs baseline: 1.3661x; 1.3661x over previous
#include <cuda_runtime.h>
#include <cstdint>

#define BB  2048
#define IN  512
#define NF  256
#define NP  256
#define EPS 1e-8f

// ---------------------------------------------------------------------------
// Device globals (allocation-free rule)
// ---------------------------------------------------------------------------
__device__ unsigned g_xq[(NF / 4) * BB];   // [f4][b] packed u8x4 of 255*sigmoid(x@W^T)
__device__ unsigned g_pq[(NF / 4) * NP];   // [f4][p] packed u8x4 of 255*sigmoid(prototypes)
__device__ float g_SxP[4 * BB];            // exact fp32 partial row sums of x_sig
__device__ float g_Sp[NP];                 // exact fp32 row sums of p_sig

__device__ __forceinline__ float sigmoidf(float v) {
    return 1.0f / (1.0f + __expf(-v));
}

__device__ __forceinline__ unsigned q8(float s) {      // s in (0,1) -> round(255 s)
    return __float2uint_rn(s * 255.0f);
}

__device__ __forceinline__ unsigned pack4(float a, float b, float c, float d) {
    return q8(a) | (q8(b) << 8) | (q8(c) << 16) | (q8(d) << 24);
}

// SIMD sum-of-absolute-differences with accumulate: d = c + sum_i |a_i - b_i|
__device__ __forceinline__ unsigned vsad_acc(unsigned a, unsigned b, unsigned c) {
    unsigned d;
    asm("vabsdiff4.u32.u32.u32.add %0, %1, %2, %3;" : "=r"(d) : "r"(a), "r"(b), "r"(c));
    return d;
}

__device__ __forceinline__ uint32_t smem_u32(const void* p) {
    uint32_t a;
    asm("{ .reg .u64 t; cvta.to.shared.u64 t, %1; cvt.u32.u64 %0, t; }"
        : "=r"(a) : "l"(p));
    return a;
}

__device__ __forceinline__ uint32_t tf32r(float v) {
    uint32_t u;
    asm("cvt.rna.tf32.f32 %0, %1;" : "=r"(u) : "f"(v));
    return u;
}

__device__ __forceinline__ void ldsm_x4(uint32_t& r0, uint32_t& r1,
                                        uint32_t& r2, uint32_t& r3, uint32_t addr) {
    asm volatile("ldmatrix.sync.aligned.m8n8.x4.shared.b16 {%0,%1,%2,%3}, [%4];"
                 : "=r"(r0), "=r"(r1), "=r"(r2), "=r"(r3) : "r"(addr));
}

__device__ __forceinline__ void mma_tf32(float* d, const uint32_t* a, const uint32_t* b) {
    asm volatile(
        "mma.sync.aligned.m16n8k8.row.col.f32.tf32.tf32.f32 "
        "{%0,%1,%2,%3}, {%4,%5,%6,%7}, {%8,%9}, {%0,%1,%2,%3};"
        : "+f"(d[0]), "+f"(d[1]), "+f"(d[2]), "+f"(d[3])
        : "r"(a[0]), "r"(a[1]), "r"(a[2]), "r"(a[3]), "r"(b[0]), "r"(b[1]));
}

// ---------------------------------------------------------------------------
// Fused Kernel: GEMM CTAs (blockIdx.x < 32) + prototype CTAs (blockIdx.x == 32)
// (unchanged — banked)
// ---------------------------------------------------------------------------
#define KC      32
#define ASTR    36                      // smem row stride in floats (144B)
#define TILE_FL (64 * ASTR)             // floats per buffer

__global__ void __launch_bounds__(256, 1)
feat_gemm_kernel(const float* __restrict__ x,
                 const float* __restrict__ features,
                 const float* __restrict__ prototypes) {
    __shared__ __align__(16) float As[2][TILE_FL];
    __shared__ __align__(16) float Bs[2][TILE_FL];

    const int tid  = threadIdx.x;

    // ======================= prototype path =======================
    if (blockIdx.x == 32) {
        float (*t)[68] = (float(*)[68])&As[0][0];     // 64 x 68 tile (17.4 KB <= As)
        const int p0 = blockIdx.y * 64;
        float spacc = 0.f;

        for (int fc = 0; fc < 4; fc++) {
            #pragma unroll
            for (int i = 0; i < 16; i++) {
                int idx = tid + i * 256;              // 0..4095
                int p = idx >> 6, f = idx & 63;
                t[p][f] = sigmoidf(prototypes[(size_t)(p0 + p) * NF + fc * 64 + f]);
            }
            __syncthreads();
            // pack 64p x 16 f4-groups -> g_pq
            #pragma unroll
            for (int i = 0; i < 4; i++) {
                int idx = tid + i * 256;              // 0..1023
                int g = idx >> 6, p = idx & 63;
                float4 v = *(const float4*)&t[p][g * 4];
                g_pq[(size_t)(fc * 16 + g) * NP + p0 + p] = pack4(v.x, v.y, v.z, v.w);
            }
            if (tid < 64) {
                float s = 0.f;
                #pragma unroll 16
                for (int f = 0; f < 64; f++) s += t[tid][f];
                spacc += s;
            }
            __syncthreads();
        }
        if (tid < 64) g_Sp[p0 + tid] = spacc;
        return;
    }

    // ========================= GEMM path =========================
    const int wid  = tid >> 5;
    const int lane = tid & 31;
    const int b0 = blockIdx.x * 64;
    const int f0 = blockIdx.y * 64;
    const int m_off = (wid & 1) * 32;        // m in {0, 32}
    const int n_off = (wid >> 1) * 16;       // n in {0, 16, 32, 48}

    int lrow[2], lkq[2];
    #pragma unroll
    for (int i = 0; i < 2; i++) {
        int idx = tid + i * 256;
        lrow[i] = idx >> 3;                  // 0..63
        lkq[i]  = idx & 7;                   // float4 slot along k
    }

    const uint32_t sA = smem_u32(As);
    const uint32_t sB = smem_u32(Bs);
    const uint32_t a_off = (uint32_t)(((lane & 15) + m_off) * ASTR + ((lane >> 4) & 1) * 4) * 4;
    const uint32_t b_off = (uint32_t)((((lane & 7) + ((lane >> 4) & 1) * 8) + n_off) * ASTR
                                      + ((lane >> 3) & 1) * 4) * 4;

    // prefetch reg sets for chunks 0 and 1 (distance-2 pipeline)
    float4 av[2][2], bv[2][2];
    #pragma unroll
    for (int s = 0; s < 2; s++)
        #pragma unroll
        for (int i = 0; i < 2; i++) {
            av[s][i] = *(const float4*)&x[(size_t)(b0 + lrow[i]) * IN + s * KC + lkq[i] * 4];
            bv[s][i] = *(const float4*)&features[(size_t)(f0 + lrow[i]) * IN + s * KC + lkq[i] * 4];
        }

    float acc[2][2][4] = {};                 // [mt][nt][4]

    #pragma unroll 2
    for (int c = 0; c < IN / KC; c++) {
        const int buf = c & 1;

        #pragma unroll
        for (int i = 0; i < 2; i++) {
            uint4 ua = make_uint4(tf32r(av[buf][i].x), tf32r(av[buf][i].y),
                                  tf32r(av[buf][i].z), tf32r(av[buf][i].w));
            uint4 ub = make_uint4(tf32r(bv[buf][i].x), tf32r(bv[buf][i].y),
                                  tf32r(bv[buf][i].z), tf32r(bv[buf][i].w));
            *(uint4*)&As[buf][lrow[i] * ASTR + lkq[i] * 4] = ua;
            *(uint4*)&Bs[buf][lrow[i] * ASTR + lkq[i] * 4] = ub;
        }

        if (c + 2 < IN / KC) {
            const int k0 = (c + 2) * KC;
            #pragma unroll
            for (int i = 0; i < 2; i++) {
                av[buf][i] = *(const float4*)&x[(size_t)(b0 + lrow[i]) * IN + k0 + lkq[i] * 4];
                bv[buf][i] = *(const float4*)&features[(size_t)(f0 + lrow[i]) * IN + k0 + lkq[i] * 4];
            }
        }

        __syncthreads();

        const uint32_t baseA = sA + (uint32_t)buf * TILE_FL * 4;
        const uint32_t baseB = sB + (uint32_t)buf * TILE_FL * 4;

        #pragma unroll
        for (int s = 0; s < 4; s++) {
            const uint32_t kb = (uint32_t)(s * 8) * 4;
            uint32_t aa[2][4], bb[4];
            ldsm_x4(aa[0][0], aa[0][1], aa[0][2], aa[0][3], baseA + a_off + kb);
            ldsm_x4(aa[1][0], aa[1][1], aa[1][2], aa[1][3], baseA + a_off + kb + 16 * ASTR * 4);
            ldsm_x4(bb[0], bb[1], bb[2], bb[3], baseB + b_off + kb);
            #pragma unroll
            for (int mt = 0; mt < 2; mt++)
                #pragma unroll
                for (int nt = 0; nt < 2; nt++)
                    mma_tf32(acc[mt][nt], aa[mt], &bb[nt * 2]);
        }
    }

    // ---- epilogue: sigmoid -> Csm [f][b]; then quantize/pack + exact Sx ----
    float* Csm = &As[0][0];                  // 64 x 68 overlay
    #define CSTR 68
    __syncthreads();

    {
        const int mrow = m_off + (lane >> 2);
        const int ncol = n_off + 2 * (lane & 3);
        #pragma unroll
        for (int mt = 0; mt < 2; mt++) {
            #pragma unroll
            for (int nt = 0; nt < 2; nt++) {
                const int m = mrow + mt * 16;
                const int n = ncol + nt * 8;
                Csm[(n    ) * CSTR + m    ] = sigmoidf(acc[mt][nt][0]);
                Csm[(n + 1) * CSTR + m    ] = sigmoidf(acc[mt][nt][1]);
                Csm[(n    ) * CSTR + m + 8] = sigmoidf(acc[mt][nt][2]);
                Csm[(n + 1) * CSTR + m + 8] = sigmoidf(acc[mt][nt][3]);
            }
        }
    }
    __syncthreads();

    // pack 16 f4-groups x 64 b -> g_xq (coalesced u32 stores)
    #pragma unroll
    for (int i = 0; i < 4; i++) {
        int idx = tid + i * 256;             // 0..1023
        int g = idx >> 6, b = idx & 63;
        unsigned q = pack4(Csm[(4 * g + 0) * CSTR + b], Csm[(4 * g + 1) * CSTR + b],
                           Csm[(4 * g + 2) * CSTR + b], Csm[(4 * g + 3) * CSTR + b]);
        g_xq[(size_t)(f0 / 4 + g) * BB + b0 + b] = q;
    }

    // exact Sx partials: threads 0..63 sum their b-column over this CTA's 64 f's
    if (tid < 64) {
        float s = 0.f;
        #pragma unroll 16
        for (int f = 0; f < 64; f++) s += Csm[f * CSTR + tid];
        g_SxP[blockIdx.y * BB + b0 + tid] = s;
    }
}

// ---------------------------------------------------------------------------
// Kernel C: Tversky core, v5 — SAD formulation.
// min(a,b) = (a + b - |a-b|)/2  =>
// I_q[b,p] = (Sxq[b] + Spq[p] - sum_f |qa - qb|) / 2   (exact integers)
// Inner loop: 1 x vabsdiff4.add per (b,p,f4).
// 512 threads, warp grid 4(b) x 4(p), lane tile 4b x 2p.  grid (32, 4).
// ---------------------------------------------------------------------------
__global__ void __launch_bounds__(512)
tversky_kernel(const float* __restrict__ bias,
               const float* __restrict__ alphap,
               const float* __restrict__ betap,
               float* __restrict__ out) {
    __shared__ unsigned xq[64][64];    // [f4][b]  16 KB (all 256 f)
    __shared__ unsigned pq[64][64];    // [f4][p]  16 KB
    __shared__ unsigned sxq_sm[64];    // quantized row sums (b)
    __shared__ unsigned spq_sm[64];    // quantized row sums (p)

    const int tid = threadIdx.x;
    const int lane = tid & 31;
    const int wid  = tid >> 5;
    const int wi = wid & 3;            // warp p index
    const int wj = wid >> 2;           // warp b index
    const int li = lane & 7;           // lane p index (x2)
    const int lj = lane >> 3;          // lane b index (x4)
    const int b0 = blockIdx.x * 64;
    const int p0 = blockIdx.y * 64;

    const int bcol = wj * 16 + lj * 4;
    const int pcol = wi * 16 + li * 2;

    // fill smem: 1024 uint4 per array, 2 per thread
    #pragma unroll
    for (int i = 0; i < 2; i++) {
        int idx = tid + i * 512;           // 0..1023
        int r = idx >> 4;                  // f4 row 0..63
        int q = (idx & 15) * 4;            // u32 quad
        *(uint4*)&xq[r][q] = *(const uint4*)&g_xq[(size_t)r * BB + b0 + q];
        *(uint4*)&pq[r][q] = *(const uint4*)&g_pq[(size_t)r * NP + p0 + q];
    }
    __syncthreads();

    // phase A: quantized row sums via dp4a (threads 0-63: b; 64-127: p)
    if (tid < 64) {
        unsigned s = 0;
        #pragma unroll 16
        for (int r = 0; r < 64; r++) s = __dp4a(xq[r][tid], 0x01010101u, s);
        sxq_sm[tid] = s;
    } else if (tid < 128) {
        const int p = tid - 64;
        unsigned s = 0;
        #pragma unroll 16
        for (int r = 0; r < 64; r++) s = __dp4a(pq[r][p], 0x01010101u, s);
        spq_sm[p] = s;
    }

    unsigned sad[4][2] = {};

    #pragma unroll 8
    for (int f4 = 0; f4 < 64; f4++) {
        uint4 a = *(const uint4*)&xq[f4][bcol];
        uint2 p = *(const uint2*)&pq[f4][pcol];
        unsigned av[4] = {a.x, a.y, a.z, a.w};
        #pragma unroll
        for (int i = 0; i < 4; i++) {
            sad[i][0] = vsad_acc(av[i], p.x, sad[i][0]);
            sad[i][1] = vsad_acc(av[i], p.y, sad[i][1]);
        }
    }
    __syncthreads();                       // sxq_sm/spq_sm visible

    const float alpha = *alphap;
    const float beta  = *betap;
    const float half255 = 0.5f / 255.0f;

    float bi[2], spv[2];
    unsigned spq[2];
    #pragma unroll
    for (int j = 0; j < 2; j++) {
        int p = p0 + pcol + j;
        bi[j]  = bias[p];
        spv[j] = g_Sp[p];
        spq[j] = spq_sm[pcol + j];
    }

    #pragma unroll
    for (int i = 0; i < 4; i++) {
        int b = b0 + bcol + i;
        float Sx = g_SxP[b] + g_SxP[BB + b] + g_SxP[2 * BB + b] + g_SxP[3 * BB + b];
        unsigned sxq = sxq_sm[bcol + i];
        float2 o;
        #pragma unroll
        for (int j = 0; j < 2; j++) {
            float I = (float)(int)(sxq + spq[j] - sad[i][j]) * half255;
            float denom = I + alpha * (Sx - I) + beta * (spv[j] - I) + EPS;
            ((float*)&o)[j] = I / denom + bi[j];
        }
        *(float2*)&out[(size_t)b * NP + p0 + pcol] = o;
    }
}

// ---------------------------------------------------------------------------
// Launch. Inputs: x, features, prototypes, bias, alpha, beta.
// ---------------------------------------------------------------------------
extern "C" void kernel_launch(void* const* d_in, const int* in_sizes, int n_in,
                              void* d_out, int out_size) {
    const float* x          = (const float*)d_in[0];
    const float* features   = (const float*)d_in[1];
    const float* prototypes = (const float*)d_in[2];
    const float* bias       = (const float*)d_in[3];
    const float* alpha      = (const float*)d_in[4];
    const float* beta       = (const float*)d_in[5];
    float* out = (float*)d_out;

    feat_gemm_kernel<<<dim3(33, 4), 256>>>(x, features, prototypes);
    tversky_kernel<<<dim3(BB / 64, NP / 64), 512>>>(bias, alpha, beta, out);
}

// round 14
// speedup vs baseline: 1.7337x; 1.2691x over previous
#include <cuda_runtime.h>
#include <cstdint>

#define BB  2048
#define IN  512
#define NF  256
#define NP  256
#define EPS 1e-8f

// ---------------------------------------------------------------------------
// Device globals (allocation-free rule)
// ---------------------------------------------------------------------------
__device__ unsigned g_xq[(NF / 4) * BB];   // [f4][b] packed u8x4 of 255*sigmoid(x@W^T)
__device__ unsigned g_pq[(NF / 4) * NP];   // [f4][p] packed u8x4 of 255*sigmoid(prototypes)
__device__ float g_SxP[4 * BB];            // exact fp32 partial row sums of x_sig
__device__ float g_Sp[NP];                 // exact fp32 row sums of p_sig
__device__ int   g_bar1 = 0;               // grid barrier: arrivals
__device__ int   g_bar2 = 0;               // grid barrier: observers (for self-reset)

#define NCTA_TOTAL 132
#define NCTA_WORK  128

__device__ __forceinline__ float sigmoidf(float v) {
    return 1.0f / (1.0f + __expf(-v));
}
__device__ __forceinline__ unsigned q8(float s) {
    return __float2uint_rn(s * 255.0f);
}
__device__ __forceinline__ unsigned pack4(float a, float b, float c, float d) {
    return q8(a) | (q8(b) << 8) | (q8(c) << 16) | (q8(d) << 24);
}
__device__ __forceinline__ unsigned vsad_acc(unsigned a, unsigned b, unsigned c) {
    unsigned d;
    asm("vabsdiff4.u32.u32.u32.add %0, %1, %2, %3;" : "=r"(d) : "r"(a), "r"(b), "r"(c));
    return d;
}
__device__ __forceinline__ uint32_t smem_u32(const void* p) {
    uint32_t a;
    asm("{ .reg .u64 t; cvta.to.shared.u64 t, %1; cvt.u32.u64 %0, t; }"
        : "=r"(a) : "l"(p));
    return a;
}
__device__ __forceinline__ uint32_t tf32r(float v) {
    uint32_t u;
    asm("cvt.rna.tf32.f32 %0, %1;" : "=r"(u) : "f"(v));
    return u;
}
__device__ __forceinline__ void ldsm_x4(uint32_t& r0, uint32_t& r1,
                                        uint32_t& r2, uint32_t& r3, uint32_t addr) {
    asm volatile("ldmatrix.sync.aligned.m8n8.x4.shared.b16 {%0,%1,%2,%3}, [%4];"
                 : "=r"(r0), "=r"(r1), "=r"(r2), "=r"(r3) : "r"(addr));
}
__device__ __forceinline__ void mma_tf32(float* d, const uint32_t* a, const uint32_t* b) {
    asm volatile(
        "mma.sync.aligned.m16n8k8.row.col.f32.tf32.tf32.f32 "
        "{%0,%1,%2,%3}, {%4,%5,%6,%7}, {%8,%9}, {%0,%1,%2,%3};"
        : "+f"(d[0]), "+f"(d[1]), "+f"(d[2]), "+f"(d[3])
        : "r"(a[0]), "r"(a[1]), "r"(a[2]), "r"(a[3]), "r"(b[0]), "r"(b[1]));
}

// ---------------------------------------------------------------------------
// Fused persistent kernel. grid = 132 CTAs x 512 threads (one wave, 148 SMs).
//   CTA 0..127 : phase 1 GEMM (b-tile = ctaid&31, f-tile = ctaid>>5)
//   CTA 128..131: phase 1 proto (p-tile = ctaid-128), arrive & exit
//   grid barrier (counter, self-resetting)
//   CTA 0..127 : phase 2 Tversky (b-tile = ctaid&31, p-tile = ctaid>>5)
// ---------------------------------------------------------------------------
#define KC      32
#define ASTR    36                          // smem row stride in floats (144B)
#define TILE_FL (64 * ASTR)                 // 2304 floats per buffer
#define SM_BYTES 36864                      // max(gemm 36864, tversky 33280)

__global__ void __launch_bounds__(512, 1)
fused_kernel(const float* __restrict__ x,
             const float* __restrict__ features,
             const float* __restrict__ prototypes,
             const float* __restrict__ bias,
             const float* __restrict__ alphap,
             const float* __restrict__ betap,
             float* __restrict__ out) {
    __shared__ __align__(16) unsigned char sm[SM_BYTES];

    const int tid  = threadIdx.x;
    const int cta  = blockIdx.x;
    const int lane = tid & 31;
    const int wid  = tid >> 5;

    // =================== PHASE 1a: prototype CTAs ===================
    if (cta >= NCTA_WORK) {
        float (*t)[68] = (float(*)[68])sm;            // 64 x 68 floats (17.4 KB)
        const int p0 = (cta - NCTA_WORK) * 64;
        float spacc = 0.f;

        for (int fc = 0; fc < 4; fc++) {
            #pragma unroll
            for (int i = 0; i < 8; i++) {
                int idx = tid + i * 512;              // 0..4095
                int p = idx >> 6, f = idx & 63;
                t[p][f] = sigmoidf(prototypes[(size_t)(p0 + p) * NF + fc * 64 + f]);
            }
            __syncthreads();
            #pragma unroll
            for (int i = 0; i < 2; i++) {
                int idx = tid + i * 512;              // 0..1023
                int g = idx >> 6, p = idx & 63;
                float4 v = *(const float4*)&t[p][g * 4];
                g_pq[(size_t)(fc * 16 + g) * NP + p0 + p] = pack4(v.x, v.y, v.z, v.w);
            }
            if (tid < 64) {
                float s = 0.f;
                #pragma unroll 16
                for (int f = 0; f < 64; f++) s += t[tid][f];
                spacc += s;
            }
            __syncthreads();
        }
        if (tid < 64) g_Sp[p0 + tid] = spacc;

        __threadfence();
        __syncthreads();
        if (tid == 0) atomicAdd(&g_bar1, 1);
        return;                                       // proto CTAs exit
    }

    // =================== PHASE 1b: GEMM CTAs ===================
    const int b0 = (cta & 31) * 64;
    const int f0 = (cta >> 5) * 64;
    {
        float* As = (float*)sm;                       // [2][TILE_FL]
        float* Bs = (float*)(sm + 2 * TILE_FL * 4);   // [2][TILE_FL]

        const int m_off = (wid & 3) * 16;             // m in {0,16,32,48}
        const int n_off = (wid >> 2) * 16;            // n in {0,16,32,48}

        const int lrow = tid >> 3;                    // 0..63
        const int lkq  = tid & 7;                     // float4 slot along k

        const uint32_t sA = smem_u32(As);
        const uint32_t sB = smem_u32(Bs);
        const uint32_t a_off = (uint32_t)(((lane & 15) + m_off) * ASTR + ((lane >> 4) & 1) * 4) * 4;
        const uint32_t b_off = (uint32_t)((((lane & 7) + ((lane >> 4) & 1) * 8) + n_off) * ASTR
                                          + ((lane >> 3) & 1) * 4) * 4;

        // prefetch chunks 0 and 1 (distance-2 pipeline), 1 float4/operand/thread
        float4 av[2], bv[2];
        #pragma unroll
        for (int s = 0; s < 2; s++) {
            av[s] = *(const float4*)&x[(size_t)(b0 + lrow) * IN + s * KC + lkq * 4];
            bv[s] = *(const float4*)&features[(size_t)(f0 + lrow) * IN + s * KC + lkq * 4];
        }

        float acc[2][4] = {};                         // [nt][4]

        #pragma unroll 2
        for (int c = 0; c < IN / KC; c++) {
            const int buf = c & 1;

            {
                uint4 ua = make_uint4(tf32r(av[buf].x), tf32r(av[buf].y),
                                      tf32r(av[buf].z), tf32r(av[buf].w));
                uint4 ub = make_uint4(tf32r(bv[buf].x), tf32r(bv[buf].y),
                                      tf32r(bv[buf].z), tf32r(bv[buf].w));
                *(uint4*)&As[buf * TILE_FL + lrow * ASTR + lkq * 4] = ua;
                *(uint4*)&Bs[buf * TILE_FL + lrow * ASTR + lkq * 4] = ub;
            }

            if (c + 2 < IN / KC) {
                const int k0 = (c + 2) * KC;
                av[buf] = *(const float4*)&x[(size_t)(b0 + lrow) * IN + k0 + lkq * 4];
                bv[buf] = *(const float4*)&features[(size_t)(f0 + lrow) * IN + k0 + lkq * 4];
            }

            __syncthreads();

            const uint32_t baseA = sA + (uint32_t)buf * TILE_FL * 4;
            const uint32_t baseB = sB + (uint32_t)buf * TILE_FL * 4;

            #pragma unroll
            for (int s = 0; s < 4; s++) {
                const uint32_t kb = (uint32_t)(s * 8) * 4;
                uint32_t aa[4], bb[4];
                ldsm_x4(aa[0], aa[1], aa[2], aa[3], baseA + a_off + kb);
                ldsm_x4(bb[0], bb[1], bb[2], bb[3], baseB + b_off + kb);
                mma_tf32(acc[0], aa, &bb[0]);
                mma_tf32(acc[1], aa, &bb[2]);
            }
        }

        // ---- epilogue: sigmoid -> Csm [f][b]; quantize/pack + exact Sx ----
        float* Csm = As;                              // 64 x 68 overlay (17.4 KB)
        #define CSTR 68
        __syncthreads();

        {
            const int m = m_off + (lane >> 2);
            const int nc0 = n_off + 2 * (lane & 3);
            #pragma unroll
            for (int nt = 0; nt < 2; nt++) {
                const int n = nc0 + nt * 8;
                Csm[(n    ) * CSTR + m    ] = sigmoidf(acc[nt][0]);
                Csm[(n + 1) * CSTR + m    ] = sigmoidf(acc[nt][1]);
                Csm[(n    ) * CSTR + m + 8] = sigmoidf(acc[nt][2]);
                Csm[(n + 1) * CSTR + m + 8] = sigmoidf(acc[nt][3]);
            }
        }
        __syncthreads();

        // pack 16 f4-groups x 64 b -> g_xq
        #pragma unroll
        for (int i = 0; i < 2; i++) {
            int idx = tid + i * 512;                  // 0..1023
            int g = idx >> 6, b = idx & 63;
            unsigned q = pack4(Csm[(4 * g + 0) * CSTR + b], Csm[(4 * g + 1) * CSTR + b],
                               Csm[(4 * g + 2) * CSTR + b], Csm[(4 * g + 3) * CSTR + b]);
            g_xq[(size_t)(f0 / 4 + g) * BB + b0 + b] = q;
        }

        if (tid < 64) {
            float s = 0.f;
            #pragma unroll 16
            for (int f = 0; f < 64; f++) s += Csm[f * CSTR + tid];
            g_SxP[(cta >> 5) * BB + b0 + tid] = s;
        }
    }

    // =================== GRID BARRIER ===================
    __threadfence();
    __syncthreads();
    if (tid == 0) {
        atomicAdd(&g_bar1, 1);
        while (*((volatile int*)&g_bar1) != NCTA_TOTAL) { }
        int obs = atomicAdd(&g_bar2, 1);
        if (obs == NCTA_WORK - 1) {                   // last observer resets
            *((volatile int*)&g_bar1) = 0;
            *((volatile int*)&g_bar2) = 0;
        }
    }
    __syncthreads();
    __threadfence();

    // =================== PHASE 2: Tversky (SAD) ===================
    {
        unsigned (*xq)[64] = (unsigned(*)[64])sm;                    // 16 KB
        unsigned (*pq)[64] = (unsigned(*)[64])(sm + 16384);          // 16 KB
        unsigned* sxq_sm = (unsigned*)(sm + 32768);                  // 256 B
        unsigned* spq_sm = (unsigned*)(sm + 33024);                  // 256 B

        const int p0 = (cta >> 5) * 64;
        const int wi = wid & 3;
        const int wj = wid >> 2;
        const int li = lane & 7;
        const int lj = lane >> 3;
        const int bcol = wj * 16 + lj * 4;
        const int pcol = wi * 16 + li * 2;

        #pragma unroll
        for (int i = 0; i < 2; i++) {
            int idx = tid + i * 512;           // 0..1023
            int r = idx >> 4;
            int q = (idx & 15) * 4;
            *(uint4*)&xq[r][q] = *(const uint4*)&g_xq[(size_t)r * BB + b0 + q];
            *(uint4*)&pq[r][q] = *(const uint4*)&g_pq[(size_t)r * NP + p0 + q];
        }
        __syncthreads();

        if (tid < 64) {
            unsigned s = 0;
            #pragma unroll 16
            for (int r = 0; r < 64; r++) s = __dp4a(xq[r][tid], 0x01010101u, s);
            sxq_sm[tid] = s;
        } else if (tid < 128) {
            const int p = tid - 64;
            unsigned s = 0;
            #pragma unroll 16
            for (int r = 0; r < 64; r++) s = __dp4a(pq[r][p], 0x01010101u, s);
            spq_sm[p] = s;
        }

        unsigned sad[4][2] = {};

        #pragma unroll 8
        for (int f4 = 0; f4 < 64; f4++) {
            uint4 a = *(const uint4*)&xq[f4][bcol];
            uint2 p = *(const uint2*)&pq[f4][pcol];
            unsigned av4[4] = {a.x, a.y, a.z, a.w};
            #pragma unroll
            for (int i = 0; i < 4; i++) {
                sad[i][0] = vsad_acc(av4[i], p.x, sad[i][0]);
                sad[i][1] = vsad_acc(av4[i], p.y, sad[i][1]);
            }
        }
        __syncthreads();

        const float alpha = *alphap;
        const float beta  = *betap;
        const float half255 = 0.5f / 255.0f;

        float bi[2], spv[2];
        unsigned spq2[2];
        #pragma unroll
        for (int j = 0; j < 2; j++) {
            int p = p0 + pcol + j;
            bi[j]   = bias[p];
            spv[j]  = g_Sp[p];
            spq2[j] = spq_sm[pcol + j];
        }

        #pragma unroll
        for (int i = 0; i < 4; i++) {
            int b = b0 + bcol + i;
            float Sx = g_SxP[b] + g_SxP[BB + b] + g_SxP[2 * BB + b] + g_SxP[3 * BB + b];
            unsigned sxq = sxq_sm[bcol + i];
            float2 o;
            #pragma unroll
            for (int j = 0; j < 2; j++) {
                float I = (float)(int)(sxq + spq2[j] - sad[i][j]) * half255;
                float denom = I + alpha * (Sx - I) + beta * (spv[j] - I) + EPS;
                ((float*)&o)[j] = I / denom + bi[j];
            }
            *(float2*)&out[(size_t)b * NP + p0 + pcol] = o;
        }
    }
}

// ---------------------------------------------------------------------------
// Launch. Inputs: x, features, prototypes, bias, alpha, beta.
// ---------------------------------------------------------------------------
extern "C" void kernel_launch(void* const* d_in, const int* in_sizes, int n_in,
                              void* d_out, int out_size) {
    const float* x          = (const float*)d_in[0];
    const float* features   = (const float*)d_in[1];
    const float* prototypes = (const float*)d_in[2];
    const float* bias       = (const float*)d_in[3];
    const float* alpha      = (const float*)d_in[4];
    const float* beta       = (const float*)d_in[5];
    float* out = (float*)d_out;

    fused_kernel<<<NCTA_TOTAL, 512>>>(x, features, prototypes, bias, alpha, beta, out);
}

// round 15
// speedup vs baseline: 1.7386x; 1.0028x over previous
#include <cuda_runtime.h>
#include <cstdint>

#define BB  2048
#define IN  512
#define NF  256
#define NP  256
#define EPS 1e-8f

// ---------------------------------------------------------------------------
// Device globals (allocation-free rule)
// ---------------------------------------------------------------------------
__device__ unsigned g_xq[(NF / 4) * BB];   // [f4][b] packed u8x4 of 255*sigmoid(x@W^T)
__device__ unsigned g_pq[(NF / 4) * NP];   // [f4][p] packed u8x4 of 255*sigmoid(prototypes)
__device__ float g_SxP[4 * BB];            // exact fp32 partial row sums of x_sig
__device__ float g_Sp[NP];                 // exact fp32 row sums of p_sig
__device__ int   g_bar1 = 0;               // grid barrier: arrivals
__device__ int   g_bar2 = 0;               // grid barrier: observers (for self-reset)

#define NCTA_TOTAL 132
#define NCTA_WORK  128

__device__ __forceinline__ float sigmoidf(float v) {
    return 1.0f / (1.0f + __expf(-v));
}
__device__ __forceinline__ unsigned q8(float s) {
    return __float2uint_rn(s * 255.0f);
}
__device__ __forceinline__ unsigned pack4(float a, float b, float c, float d) {
    return q8(a) | (q8(b) << 8) | (q8(c) << 16) | (q8(d) << 24);
}
__device__ __forceinline__ unsigned vsad_acc(unsigned a, unsigned b, unsigned c) {
    unsigned d;
    asm("vabsdiff4.u32.u32.u32.add %0, %1, %2, %3;" : "=r"(d) : "r"(a), "r"(b), "r"(c));
    return d;
}
__device__ __forceinline__ uint32_t smem_u32(const void* p) {
    uint32_t a;
    asm("{ .reg .u64 t; cvta.to.shared.u64 t, %1; cvt.u32.u64 %0, t; }"
        : "=r"(a) : "l"(p));
    return a;
}
__device__ __forceinline__ uint32_t tf32r(float v) {
    uint32_t u;
    asm("cvt.rna.tf32.f32 %0, %1;" : "=r"(u) : "f"(v));
    return u;
}
__device__ __forceinline__ void ldsm_x4(uint32_t& r0, uint32_t& r1,
                                        uint32_t& r2, uint32_t& r3, uint32_t addr) {
    asm volatile("ldmatrix.sync.aligned.m8n8.x4.shared.b16 {%0,%1,%2,%3}, [%4];"
                 : "=r"(r0), "=r"(r1), "=r"(r2), "=r"(r3) : "r"(addr));
}
__device__ __forceinline__ void mma_tf32(float* d, const uint32_t* a, const uint32_t* b) {
    asm volatile(
        "mma.sync.aligned.m16n8k8.row.col.f32.tf32.tf32.f32 "
        "{%0,%1,%2,%3}, {%4,%5,%6,%7}, {%8,%9}, {%0,%1,%2,%3};"
        : "+f"(d[0]), "+f"(d[1]), "+f"(d[2]), "+f"(d[3])
        : "r"(a[0]), "r"(a[1]), "r"(a[2]), "r"(a[3]), "r"(b[0]), "r"(b[1]));
}

// ---------------------------------------------------------------------------
// Fused persistent kernel. grid = 132 CTAs x 512 threads (one wave).
//   CTA 0..127 : phase 1 GEMM; CTA 128..131: proto (arrive & exit);
//   grid barrier; CTA 0..127 : phase 2 Tversky.
// GEMM phase: register prefetch distance 4 (covers ~1000 cyc of LDG latency).
// ---------------------------------------------------------------------------
#define KC      32
#define ASTR    36                          // smem row stride in floats (144B)
#define TILE_FL (64 * ASTR)                 // 2304 floats per buffer
#define SM_BYTES 36864                      // max(gemm 36864, tversky 33280)

__global__ void __launch_bounds__(512, 1)
fused_kernel(const float* __restrict__ x,
             const float* __restrict__ features,
             const float* __restrict__ prototypes,
             const float* __restrict__ bias,
             const float* __restrict__ alphap,
             const float* __restrict__ betap,
             float* __restrict__ out) {
    __shared__ __align__(16) unsigned char sm[SM_BYTES];

    const int tid  = threadIdx.x;
    const int cta  = blockIdx.x;
    const int lane = tid & 31;
    const int wid  = tid >> 5;

    // =================== PHASE 1a: prototype CTAs ===================
    if (cta >= NCTA_WORK) {
        float (*t)[68] = (float(*)[68])sm;            // 64 x 68 floats (17.4 KB)
        const int p0 = (cta - NCTA_WORK) * 64;
        float spacc = 0.f;

        for (int fc = 0; fc < 4; fc++) {
            #pragma unroll
            for (int i = 0; i < 8; i++) {
                int idx = tid + i * 512;              // 0..4095
                int p = idx >> 6, f = idx & 63;
                t[p][f] = sigmoidf(prototypes[(size_t)(p0 + p) * NF + fc * 64 + f]);
            }
            __syncthreads();
            #pragma unroll
            for (int i = 0; i < 2; i++) {
                int idx = tid + i * 512;              // 0..1023
                int g = idx >> 6, p = idx & 63;
                float4 v = *(const float4*)&t[p][g * 4];
                g_pq[(size_t)(fc * 16 + g) * NP + p0 + p] = pack4(v.x, v.y, v.z, v.w);
            }
            if (tid < 64) {
                float s = 0.f;
                #pragma unroll 16
                for (int f = 0; f < 64; f++) s += t[tid][f];
                spacc += s;
            }
            __syncthreads();
        }
        if (tid < 64) g_Sp[p0 + tid] = spacc;

        __threadfence();
        __syncthreads();
        if (tid == 0) atomicAdd(&g_bar1, 1);
        return;                                       // proto CTAs exit
    }

    // =================== PHASE 1b: GEMM CTAs ===================
    const int b0 = (cta & 31) * 64;
    const int f0 = (cta >> 5) * 64;
    {
        float* As = (float*)sm;                       // [2][TILE_FL]
        float* Bs = (float*)(sm + 2 * TILE_FL * 4);   // [2][TILE_FL]

        const int m_off = (wid & 3) * 16;             // m in {0,16,32,48}
        const int n_off = (wid >> 2) * 16;            // n in {0,16,32,48}

        const int lrow = tid >> 3;                    // 0..63
        const int lkq  = tid & 7;                     // float4 slot along k

        const uint32_t sA = smem_u32(As);
        const uint32_t sB = smem_u32(Bs);
        const uint32_t a_off = (uint32_t)(((lane & 15) + m_off) * ASTR + ((lane >> 4) & 1) * 4) * 4;
        const uint32_t b_off = (uint32_t)((((lane & 7) + ((lane >> 4) & 1) * 8) + n_off) * ASTR
                                          + ((lane >> 3) & 1) * 4) * 4;

        const float* xrow = &x[(size_t)(b0 + lrow) * IN + lkq * 4];
        const float* wrow = &features[(size_t)(f0 + lrow) * IN + lkq * 4];

        // prefetch chunks 0..3 (distance-4 register pipeline)
        float4 av[4], bv[4];
        #pragma unroll
        for (int s = 0; s < 4; s++) {
            av[s] = *(const float4*)&xrow[s * KC];
            bv[s] = *(const float4*)&wrow[s * KC];
        }

        float acc[2][4] = {};                         // [nt][4]

        #pragma unroll 4
        for (int c = 0; c < IN / KC; c++) {
            const int slot = c & 3;
            const int buf  = c & 1;

            {
                uint4 ua = make_uint4(tf32r(av[slot].x), tf32r(av[slot].y),
                                      tf32r(av[slot].z), tf32r(av[slot].w));
                uint4 ub = make_uint4(tf32r(bv[slot].x), tf32r(bv[slot].y),
                                      tf32r(bv[slot].z), tf32r(bv[slot].w));
                *(uint4*)&As[buf * TILE_FL + lrow * ASTR + lkq * 4] = ua;
                *(uint4*)&Bs[buf * TILE_FL + lrow * ASTR + lkq * 4] = ub;
            }

            if (c + 4 < IN / KC) {
                av[slot] = *(const float4*)&xrow[(c + 4) * KC];
                bv[slot] = *(const float4*)&wrow[(c + 4) * KC];
            }

            __syncthreads();

            const uint32_t baseA = sA + (uint32_t)buf * TILE_FL * 4;
            const uint32_t baseB = sB + (uint32_t)buf * TILE_FL * 4;

            #pragma unroll
            for (int s = 0; s < 4; s++) {
                const uint32_t kb = (uint32_t)(s * 8) * 4;
                uint32_t aa[4], bb[4];
                ldsm_x4(aa[0], aa[1], aa[2], aa[3], baseA + a_off + kb);
                ldsm_x4(bb[0], bb[1], bb[2], bb[3], baseB + b_off + kb);
                mma_tf32(acc[0], aa, &bb[0]);
                mma_tf32(acc[1], aa, &bb[2]);
            }
        }

        // ---- epilogue: sigmoid -> Csm [f][b]; quantize/pack + exact Sx ----
        float* Csm = As;                              // 64 x 68 overlay (17.4 KB)
        #define CSTR 68
        __syncthreads();

        {
            const int m = m_off + (lane >> 2);
            const int nc0 = n_off + 2 * (lane & 3);
            #pragma unroll
            for (int nt = 0; nt < 2; nt++) {
                const int n = nc0 + nt * 8;
                Csm[(n    ) * CSTR + m    ] = sigmoidf(acc[nt][0]);
                Csm[(n + 1) * CSTR + m    ] = sigmoidf(acc[nt][1]);
                Csm[(n    ) * CSTR + m + 8] = sigmoidf(acc[nt][2]);
                Csm[(n + 1) * CSTR + m + 8] = sigmoidf(acc[nt][3]);
            }
        }
        __syncthreads();

        // pack 16 f4-groups x 64 b -> g_xq
        #pragma unroll
        for (int i = 0; i < 2; i++) {
            int idx = tid + i * 512;                  // 0..1023
            int g = idx >> 6, b = idx & 63;
            unsigned q = pack4(Csm[(4 * g + 0) * CSTR + b], Csm[(4 * g + 1) * CSTR + b],
                               Csm[(4 * g + 2) * CSTR + b], Csm[(4 * g + 3) * CSTR + b]);
            g_xq[(size_t)(f0 / 4 + g) * BB + b0 + b] = q;
        }

        if (tid < 64) {
            float s = 0.f;
            #pragma unroll 16
            for (int f = 0; f < 64; f++) s += Csm[f * CSTR + tid];
            g_SxP[(cta >> 5) * BB + b0 + tid] = s;
        }
    }

    // =================== GRID BARRIER ===================
    __threadfence();
    __syncthreads();
    if (tid == 0) {
        atomicAdd(&g_bar1, 1);
        while (*((volatile int*)&g_bar1) != NCTA_TOTAL) { }
        int obs = atomicAdd(&g_bar2, 1);
        if (obs == NCTA_WORK - 1) {                   // last observer resets
            *((volatile int*)&g_bar1) = 0;
            *((volatile int*)&g_bar2) = 0;
        }
    }
    __syncthreads();
    __threadfence();

    // =================== PHASE 2: Tversky (SAD) ===================
    {
        unsigned (*xq)[64] = (unsigned(*)[64])sm;                    // 16 KB
        unsigned (*pq)[64] = (unsigned(*)[64])(sm + 16384);          // 16 KB
        unsigned* sxq_sm = (unsigned*)(sm + 32768);                  // 256 B
        unsigned* spq_sm = (unsigned*)(sm + 33024);                  // 256 B

        const int p0 = (cta >> 5) * 64;
        const int wi = wid & 3;
        const int wj = wid >> 2;
        const int li = lane & 7;
        const int lj = lane >> 3;
        const int bcol = wj * 16 + lj * 4;
        const int pcol = wi * 16 + li * 2;

        #pragma unroll
        for (int i = 0; i < 2; i++) {
            int idx = tid + i * 512;           // 0..1023
            int r = idx >> 4;
            int q = (idx & 15) * 4;
            *(uint4*)&xq[r][q] = *(const uint4*)&g_xq[(size_t)r * BB + b0 + q];
            *(uint4*)&pq[r][q] = *(const uint4*)&g_pq[(size_t)r * NP + p0 + q];
        }
        __syncthreads();

        if (tid < 64) {
            unsigned s = 0;
            #pragma unroll 16
            for (int r = 0; r < 64; r++) s = __dp4a(xq[r][tid], 0x01010101u, s);
            sxq_sm[tid] = s;
        } else if (tid < 128) {
            const int p = tid - 64;
            unsigned s = 0;
            #pragma unroll 16
            for (int r = 0; r < 64; r++) s = __dp4a(pq[r][p], 0x01010101u, s);
            spq_sm[p] = s;
        }

        unsigned sad[4][2] = {};

        #pragma unroll 8
        for (int f4 = 0; f4 < 64; f4++) {
            uint4 a = *(const uint4*)&xq[f4][bcol];
            uint2 p = *(const uint2*)&pq[f4][pcol];
            unsigned av4[4] = {a.x, a.y, a.z, a.w};
            #pragma unroll
            for (int i = 0; i < 4; i++) {
                sad[i][0] = vsad_acc(av4[i], p.x, sad[i][0]);
                sad[i][1] = vsad_acc(av4[i], p.y, sad[i][1]);
            }
        }
        __syncthreads();

        const float alpha = *alphap;
        const float beta  = *betap;
        const float half255 = 0.5f / 255.0f;

        float bi[2], spv[2];
        unsigned spq2[2];
        #pragma unroll
        for (int j = 0; j < 2; j++) {
            int p = p0 + pcol + j;
            bi[j]   = bias[p];
            spv[j]  = g_Sp[p];
            spq2[j] = spq_sm[pcol + j];
        }

        #pragma unroll
        for (int i = 0; i < 4; i++) {
            int b = b0 + bcol + i;
            float Sx = g_SxP[b] + g_SxP[BB + b] + g_SxP[2 * BB + b] + g_SxP[3 * BB + b];
            unsigned sxq = sxq_sm[bcol + i];
            float2 o;
            #pragma unroll
            for (int j = 0; j < 2; j++) {
                float I = (float)(int)(sxq + spq2[j] - sad[i][j]) * half255;
                float denom = I + alpha * (Sx - I) + beta * (spv[j] - I) + EPS;
                ((float*)&o)[j] = I / denom + bi[j];
            }
            *(float2*)&out[(size_t)b * NP + p0 + pcol] = o;
        }
    }
}

// ---------------------------------------------------------------------------
// Launch. Inputs: x, features, prototypes, bias, alpha, beta.
// ---------------------------------------------------------------------------
extern "C" void kernel_launch(void* const* d_in, const int* in_sizes, int n_in,
                              void* d_out, int out_size) {
    const float* x          = (const float*)d_in[0];
    const float* features   = (const float*)d_in[1];
    const float* prototypes = (const float*)d_in[2];
    const float* bias       = (const float*)d_in[3];
    const float* alpha      = (const float*)d_in[4];
    const float* beta       = (const float*)d_in[5];
    float* out = (float*)d_out;

    fused_kernel<<<NCTA_TOTAL, 512>>>(x, features, prototypes, bias, alpha, beta, out);
}

// round 16
// speedup vs baseline: 1.8462x; 1.0618x over previous
#include <cuda_runtime.h>
#include <cstdint>

#define BB  2048
#define IN  512
#define NF  256
#define NP  256
#define EPS 1e-8f

// ---------------------------------------------------------------------------
// Device globals (allocation-free rule)
// ---------------------------------------------------------------------------
__device__ unsigned g_xq[(NF / 4) * BB];   // [f4][b] packed u8x4 of 255*sigmoid(x@W^T)
__device__ unsigned g_pq[(NF / 4) * NP];   // [f4][p] packed u8x4 of 255*sigmoid(prototypes)
__device__ float g_SxP[4 * BB];            // exact fp32 partial row sums of x_sig
__device__ float g_Sp[NP];                 // exact fp32 row sums of p_sig
__device__ int   g_bar1 = 0;               // grid barrier: arrivals
__device__ int   g_bar2 = 0;               // grid barrier: observers (for self-reset)

#define NCTA 128

__device__ __forceinline__ float sigmoidf(float v) {
    return 1.0f / (1.0f + __expf(-v));
}
__device__ __forceinline__ unsigned q8(float s) {
    return __float2uint_rn(s * 255.0f);
}
__device__ __forceinline__ unsigned pack4(float a, float b, float c, float d) {
    return q8(a) | (q8(b) << 8) | (q8(c) << 16) | (q8(d) << 24);
}
__device__ __forceinline__ unsigned vsad_acc(unsigned a, unsigned b, unsigned c) {
    unsigned d;
    asm("vabsdiff4.u32.u32.u32.add %0, %1, %2, %3;" : "=r"(d) : "r"(a), "r"(b), "r"(c));
    return d;
}
__device__ __forceinline__ uint32_t smem_u32(const void* p) {
    uint32_t a;
    asm("{ .reg .u64 t; cvta.to.shared.u64 t, %1; cvt.u32.u64 %0, t; }"
        : "=r"(a) : "l"(p));
    return a;
}
__device__ __forceinline__ uint32_t tf32r(float v) {
    uint32_t u;
    asm("cvt.rna.tf32.f32 %0, %1;" : "=r"(u) : "f"(v));
    return u;
}
__device__ __forceinline__ void ldsm_x4(uint32_t& r0, uint32_t& r1,
                                        uint32_t& r2, uint32_t& r3, uint32_t addr) {
    asm volatile("ldmatrix.sync.aligned.m8n8.x4.shared.b16 {%0,%1,%2,%3}, [%4];"
                 : "=r"(r0), "=r"(r1), "=r"(r2), "=r"(r3) : "r"(addr));
}
__device__ __forceinline__ void mma_tf32(float* d, const uint32_t* a, const uint32_t* b) {
    asm volatile(
        "mma.sync.aligned.m16n8k8.row.col.f32.tf32.tf32.f32 "
        "{%0,%1,%2,%3}, {%4,%5,%6,%7}, {%8,%9}, {%0,%1,%2,%3};"
        : "+f"(d[0]), "+f"(d[1]), "+f"(d[2]), "+f"(d[3])
        : "r"(a[0]), "r"(a[1]), "r"(a[2]), "r"(a[3]), "r"(b[0]), "r"(b[1]));
}

// ---------------------------------------------------------------------------
// Fused persistent kernel. grid = 128 CTAs x 512 threads (one wave).
//   Phase 0: distributed proto prep — each CTA handles 2 p-rows (overlapped
//            with the GEMM register prefetch already in flight).
//   Phase 1: GEMM (b-tile = ctaid&31, f-tile = ctaid>>5)
//   grid barrier
//   Phase 2: Tversky (b-tile = ctaid&31, p-tile = ctaid>>5)
// ---------------------------------------------------------------------------
#define KC      32
#define ASTR    36                          // smem row stride in floats (144B)
#define TILE_FL (64 * ASTR)                 // 2304 floats per buffer
#define SM_BYTES 36864                      // max(gemm 36864, tversky 33280)

__global__ void __launch_bounds__(512, 1)
fused_kernel(const float* __restrict__ x,
             const float* __restrict__ features,
             const float* __restrict__ prototypes,
             const float* __restrict__ bias,
             const float* __restrict__ alphap,
             const float* __restrict__ betap,
             float* __restrict__ out) {
    __shared__ __align__(16) unsigned char sm[SM_BYTES];

    const int tid  = threadIdx.x;
    const int cta  = blockIdx.x;
    const int lane = tid & 31;
    const int wid  = tid >> 5;

    const int b0 = (cta & 31) * 64;
    const int f0 = (cta >> 5) * 64;

    // =================== GEMM prefetch (issue LDGs first) ===================
    const int lrow = tid >> 3;                    // 0..63
    const int lkq  = tid & 7;                     // float4 slot along k
    const float* xrow = &x[(size_t)(b0 + lrow) * IN + lkq * 4];
    const float* wrow = &features[(size_t)(f0 + lrow) * IN + lkq * 4];

    float4 av[4], bv[4];
    #pragma unroll
    for (int s = 0; s < 4; s++) {
        av[s] = *(const float4*)&xrow[s * KC];
        bv[s] = *(const float4*)&wrow[s * KC];
    }

    // =================== PHASE 0: distributed proto (2 p-rows/CTA) =========
    {
        float* st   = (float*)sm;                 // 2 x 256 staging (2 KB)
        float* part = (float*)(sm + 2048);        // 32 partials
        const int r = tid >> 8;                   // 0..1
        const int f = tid & 255;
        st[r * 256 + f] = sigmoidf(prototypes[(size_t)(cta * 2 + r) * NF + f]);
        __syncthreads();
        if (tid < 128) {
            int r2 = tid >> 6, g = tid & 63;
            float4 v = *(const float4*)&st[r2 * 256 + g * 4];
            g_pq[(size_t)g * NP + cta * 2 + r2] = pack4(v.x, v.y, v.z, v.w);
        } else if (tid < 160) {
            int t = tid - 128;                    // 0..31
            int r2 = t >> 4, seg = t & 15;
            float ssum = 0.f;
            #pragma unroll
            for (int i = 0; i < 16; i++) ssum += st[r2 * 256 + seg * 16 + i];
            part[t] = ssum;
        }
        __syncthreads();
        if (tid < 2) {
            float ssum = 0.f;
            #pragma unroll
            for (int i = 0; i < 16; i++) ssum += part[tid * 16 + i];
            g_Sp[cta * 2 + tid] = ssum;
        }
        __syncthreads();                          // st/part dead; smem free for GEMM
    }

    // =================== PHASE 1: GEMM ===================
    {
        float* As = (float*)sm;                       // [2][TILE_FL]
        float* Bs = (float*)(sm + 2 * TILE_FL * 4);   // [2][TILE_FL]

        const int m_off = (wid & 3) * 16;             // m in {0,16,32,48}
        const int n_off = (wid >> 2) * 16;            // n in {0,16,32,48}

        const uint32_t sA = smem_u32(As);
        const uint32_t sB = smem_u32(Bs);
        const uint32_t a_off = (uint32_t)(((lane & 15) + m_off) * ASTR + ((lane >> 4) & 1) * 4) * 4;
        const uint32_t b_off = (uint32_t)((((lane & 7) + ((lane >> 4) & 1) * 8) + n_off) * ASTR
                                          + ((lane >> 3) & 1) * 4) * 4;

        float acc[2][4] = {};                         // [nt][4]

        #pragma unroll 4
        for (int c = 0; c < IN / KC; c++) {
            const int slot = c & 3;
            const int buf  = c & 1;

            {
                uint4 ua = make_uint4(tf32r(av[slot].x), tf32r(av[slot].y),
                                      tf32r(av[slot].z), tf32r(av[slot].w));
                uint4 ub = make_uint4(tf32r(bv[slot].x), tf32r(bv[slot].y),
                                      tf32r(bv[slot].z), tf32r(bv[slot].w));
                *(uint4*)&As[buf * TILE_FL + lrow * ASTR + lkq * 4] = ua;
                *(uint4*)&Bs[buf * TILE_FL + lrow * ASTR + lkq * 4] = ub;
            }

            if (c + 4 < IN / KC) {
                av[slot] = *(const float4*)&xrow[(c + 4) * KC];
                bv[slot] = *(const float4*)&wrow[(c + 4) * KC];
            }

            __syncthreads();

            const uint32_t baseA = sA + (uint32_t)buf * TILE_FL * 4;
            const uint32_t baseB = sB + (uint32_t)buf * TILE_FL * 4;

            #pragma unroll
            for (int s = 0; s < 4; s++) {
                const uint32_t kb = (uint32_t)(s * 8) * 4;
                uint32_t aa[4], bb[4];
                ldsm_x4(aa[0], aa[1], aa[2], aa[3], baseA + a_off + kb);
                ldsm_x4(bb[0], bb[1], bb[2], bb[3], baseB + b_off + kb);
                mma_tf32(acc[0], aa, &bb[0]);
                mma_tf32(acc[1], aa, &bb[2]);
            }
        }

        // ---- epilogue: sigmoid -> Csm [f][b]; quantize/pack + exact Sx ----
        float* Csm = As;                              // 64 x 68 overlay (17.4 KB)
        #define CSTR 68
        __syncthreads();

        {
            const int m = m_off + (lane >> 2);
            const int nc0 = n_off + 2 * (lane & 3);
            #pragma unroll
            for (int nt = 0; nt < 2; nt++) {
                const int n = nc0 + nt * 8;
                Csm[(n    ) * CSTR + m    ] = sigmoidf(acc[nt][0]);
                Csm[(n + 1) * CSTR + m    ] = sigmoidf(acc[nt][1]);
                Csm[(n    ) * CSTR + m + 8] = sigmoidf(acc[nt][2]);
                Csm[(n + 1) * CSTR + m + 8] = sigmoidf(acc[nt][3]);
            }
        }
        __syncthreads();

        // pack 16 f4-groups x 64 b -> g_xq
        #pragma unroll
        for (int i = 0; i < 2; i++) {
            int idx = tid + i * 512;                  // 0..1023
            int g = idx >> 6, b = idx & 63;
            unsigned q = pack4(Csm[(4 * g + 0) * CSTR + b], Csm[(4 * g + 1) * CSTR + b],
                               Csm[(4 * g + 2) * CSTR + b], Csm[(4 * g + 3) * CSTR + b]);
            g_xq[(size_t)(f0 / 4 + g) * BB + b0 + b] = q;
        }

        if (tid < 64) {
            float s = 0.f;
            #pragma unroll 16
            for (int f = 0; f < 64; f++) s += Csm[f * CSTR + tid];
            g_SxP[(cta >> 5) * BB + b0 + tid] = s;
        }
    }

    // =================== GRID BARRIER ===================
    __threadfence();
    __syncthreads();
    if (tid == 0) {
        atomicAdd(&g_bar1, 1);
        while (*((volatile int*)&g_bar1) != NCTA) { }
        int obs = atomicAdd(&g_bar2, 1);
        if (obs == NCTA - 1) {                        // last observer resets
            *((volatile int*)&g_bar1) = 0;
            *((volatile int*)&g_bar2) = 0;
        }
    }
    __syncthreads();
    __threadfence();

    // =================== PHASE 2: Tversky (SAD) ===================
    {
        unsigned (*xq)[64] = (unsigned(*)[64])sm;                    // 16 KB
        unsigned (*pq)[64] = (unsigned(*)[64])(sm + 16384);          // 16 KB
        unsigned* sxq_sm = (unsigned*)(sm + 32768);                  // 256 B
        unsigned* spq_sm = (unsigned*)(sm + 33024);                  // 256 B

        const int p0 = (cta >> 5) * 64;
        const int wi = wid & 3;
        const int wj = wid >> 2;
        const int li = lane & 7;
        const int lj = lane >> 3;
        const int bcol = wj * 16 + lj * 4;
        const int pcol = wi * 16 + li * 2;

        #pragma unroll
        for (int i = 0; i < 2; i++) {
            int idx = tid + i * 512;           // 0..1023
            int r = idx >> 4;
            int q = (idx & 15) * 4;
            *(uint4*)&xq[r][q] = *(const uint4*)&g_xq[(size_t)r * BB + b0 + q];
            *(uint4*)&pq[r][q] = *(const uint4*)&g_pq[(size_t)r * NP + p0 + q];
        }
        __syncthreads();

        if (tid < 64) {
            unsigned s = 0;
            #pragma unroll 16
            for (int r = 0; r < 64; r++) s = __dp4a(xq[r][tid], 0x01010101u, s);
            sxq_sm[tid] = s;
        } else if (tid < 128) {
            const int p = tid - 64;
            unsigned s = 0;
            #pragma unroll 16
            for (int r = 0; r < 64; r++) s = __dp4a(pq[r][p], 0x01010101u, s);
            spq_sm[p] = s;
        }

        unsigned sad[4][2] = {};

        #pragma unroll 8
        for (int f4 = 0; f4 < 64; f4++) {
            uint4 a = *(const uint4*)&xq[f4][bcol];
            uint2 p = *(const uint2*)&pq[f4][pcol];
            unsigned av4[4] = {a.x, a.y, a.z, a.w};
            #pragma unroll
            for (int i = 0; i < 4; i++) {
                sad[i][0] = vsad_acc(av4[i], p.x, sad[i][0]);
                sad[i][1] = vsad_acc(av4[i], p.y, sad[i][1]);
            }
        }
        __syncthreads();

        const float alpha = *alphap;
        const float beta  = *betap;
        const float half255 = 0.5f / 255.0f;

        float bi[2], spv[2];
        unsigned spq2[2];
        #pragma unroll
        for (int j = 0; j < 2; j++) {
            int p = p0 + pcol + j;
            bi[j]   = bias[p];
            spv[j]  = g_Sp[p];
            spq2[j] = spq_sm[pcol + j];
        }

        #pragma unroll
        for (int i = 0; i < 4; i++) {
            int b = b0 + bcol + i;
            float Sx = g_SxP[b] + g_SxP[BB + b] + g_SxP[2 * BB + b] + g_SxP[3 * BB + b];
            unsigned sxq = sxq_sm[bcol + i];
            float2 o;
            #pragma unroll
            for (int j = 0; j < 2; j++) {
                float I = (float)(int)(sxq + spq2[j] - sad[i][j]) * half255;
                float denom = I + alpha * (Sx - I) + beta * (spv[j] - I) + EPS;
                ((float*)&o)[j] = I / denom + bi[j];
            }
            *(float2*)&out[(size_t)b * NP + p0 + pcol] = o;
        }
    }
}

// ---------------------------------------------------------------------------
// Launch. Inputs: x, features, prototypes, bias, alpha, beta.
// ---------------------------------------------------------------------------
extern "C" void kernel_launch(void* const* d_in, const int* in_sizes, int n_in,
                              void* d_out, int out_size) {
    const float* x          = (const float*)d_in[0];
    const float* features   = (const float*)d_in[1];
    const float* prototypes = (const float*)d_in[2];
    const float* bias       = (const float*)d_in[3];
    const float* alpha      = (const float*)d_in[4];
    const float* beta       = (const float*)d_in[5];
    float* out = (float*)d_out;

    fused_kernel<<<NCTA, 512>>>(x, features, prototypes, bias, alpha, beta, out);
}